// round 8
// baseline (speedup 1.0000x reference)
#include <cuda_runtime.h>
#include <cuda_fp16.h>
#include <cstdint>

#define IMH 64
#define IMW 64
#define HW 4096
#define CIN 256
#define COUT 256
#define KKTAP 9
#define KDIM 2304            // k' = kk*256 + c
#define NDIM 16384

// cols_T: [NDIM][KDIM] fp16 (row = 4608 B)  — B operand, K-major
__device__ uint4 g_colsT4[(size_t)NDIM * 288];
// repacked weight: [COUT][KDIM] fp16, same k' order — A operand, K-major
__device__ uint4 g_wr4[(size_t)COUT * 288];
// NHWC parity-pair x: [b*64+row][wq][c] as half2 words.
// wq<32: pair (x[2j],x[2j+1]); wq=32+j: pair (x[2j+1],x[2j+2]) (clamped)
__device__ uint32_t g_xh2[(size_t)4 * IMH * 64 * CIN];

__device__ __forceinline__ uint32_t smem_u32(const void* p) {
    return (uint32_t)__cvta_generic_to_shared(p);
}
__device__ __forceinline__ void cp16(uint32_t d, const void* s) {
    asm volatile("cp.async.cg.shared.global [%0], [%1], 16;" :: "r"(d), "l"(s) : "memory");
}
#define CP_COMMIT() asm volatile("cp.async.commit_group;" ::: "memory")
#define CP_WAIT2()  asm volatile("cp.async.wait_group 2;" ::: "memory")
#define CP_WAIT1()  asm volatile("cp.async.wait_group 1;" ::: "memory")
#define CP_WAIT0()  asm volatile("cp.async.wait_group 0;" ::: "memory")

#define LDSM_X4(r0, r1, r2, r3, a)                                          \
    asm volatile("ldmatrix.sync.aligned.m8n8.x4.shared.b16 {%0,%1,%2,%3}, [%4];" \
                 : "=r"(r0), "=r"(r1), "=r"(r2), "=r"(r3) : "r"(a))

#define MMA16816(c, av, bv0, bv1)                                           \
    asm volatile("mma.sync.aligned.m16n8k16.row.col.f32.f16.f16.f32 "       \
                 "{%0,%1,%2,%3}, {%4,%5,%6,%7}, {%8,%9}, {%0,%1,%2,%3};"    \
                 : "+f"((c)[0]), "+f"((c)[1]), "+f"((c)[2]), "+f"((c)[3])   \
                 : "r"((av)[0]), "r"((av)[1]), "r"((av)[2]), "r"((av)[3]),  \
                   "r"(bv0), "r"(bv1))

// ---------------- Kernel A: x NCHW fp32 -> NHWC parity-pair fp16 -----------
__global__ __launch_bounds__(256) void xpack_kernel(const float* __restrict__ x) {
    const int blk = blockIdx.x;            // b*64 + row
    const int c = threadIdx.x;
    const float* src = x + ((size_t)(blk >> 6) * CIN + c) * HW + (blk & 63) * 64;
    float v[64];
    #pragma unroll
    for (int i = 0; i < 16; i++) {
        float4 t = reinterpret_cast<const float4*>(src)[i];
        v[4 * i] = t.x; v[4 * i + 1] = t.y; v[4 * i + 2] = t.z; v[4 * i + 3] = t.w;
    }
    uint32_t w[64];
    #pragma unroll
    for (int j = 0; j < 32; j++) {
        __half2 h = __floats2half2_rn(v[2 * j], v[2 * j + 1]);
        w[j] = *reinterpret_cast<uint32_t*>(&h);
    }
    #pragma unroll
    for (int j = 0; j < 32; j++) {
        float nx = (j == 31) ? v[63] : v[2 * j + 2];
        __half2 h = __floats2half2_rn(v[2 * j + 1], nx);
        w[32 + j] = *reinterpret_cast<uint32_t*>(&h);
    }
    uint32_t* dst = g_xh2 + (size_t)blk * 64 * 256 + c;
    #pragma unroll
    for (int q = 0; q < 64; q++) dst[q * 256] = w[q];   // coalesced across c
}

// ---------------- Kernel 0: weight repack fp32->fp16, k' = kk*256+c --------
__global__ __launch_bounds__(512) void repack_kernel(const float* __restrict__ w) {
    int idx = blockIdx.x * 512 + threadIdx.x;
    int o = idx / KDIM;
    int r = idx - o * KDIM;
    int kk = r >> 8;
    int c = r & 255;
    reinterpret_cast<__half*>(g_wr4)[idx] = __float2half(w[(o * CIN + c) * KKTAP + kk]);
}

// ---------------- Kernel 1: gather, warp = one tap, coalesced NHWC ---------
__global__ __launch_bounds__(256) void gather_kernel(const float* __restrict__ offset) {
    const int gw = (blockIdx.x * 256 + threadIdx.x) >> 5;   // tap id < 147456
    const int lane = threadIdx.x & 31;
    const int n = gw / 9;
    const int kk = gw - n * 9;
    const int b = n >> 12, hw = n & 4095, ho = hw >> 6, wo = hw & 63;

    const float* offb = offset + (size_t)b * (2 * KKTAP) * HW;
    float offy = offb[(2 * kk) * HW + hw];                  // warp-broadcast
    float offx = offb[(2 * kk + 1) * HW + hw];
    float py = (float)(ho - 1 + kk / 3) + offy;
    float px = (float)(wo - 1 + kk % 3) + offx;

    float fy = floorf(py), fx = floorf(px);
    float ly = py - fy, lx = px - fx;
    int y0 = (int)fy, x0 = (int)fx, y1 = y0 + 1, x1 = x0 + 1;
    bool vy0 = (y0 >= 0) & (y0 < IMH), vy1 = (y1 >= 0) & (y1 < IMH);
    bool vx0 = (x0 >= 0) & (x0 < IMW), vx1 = (x1 >= 0) & (x1 < IMW);
    float w00 = (1.f - ly) * (1.f - lx) * (float)(vy0 & vx0);
    float w01 = (1.f - ly) * lx * (float)(vy0 & vx1);
    float w10 = ly * (1.f - lx) * (float)(vy1 & vx0);
    float w11 = ly * lx * (float)(vy1 & vx1);

    int qx = min(max(x0, 0), 62);
    int wq = (qx & 1) ? (32 + (qx >> 1)) : (qx >> 1);
    bool sel0 = (x0 == qx);
    bool sel1 = (x1 == qx);
    float wl0 = (sel0 ? w00 : 0.f) + (sel1 ? w01 : 0.f);
    float wh0 = (sel0 ? 0.f : w00) + (sel1 ? 0.f : w01);
    float wl1 = (sel0 ? w10 : 0.f) + (sel1 ? w11 : 0.f);
    float wh1 = (sel0 ? 0.f : w10) + (sel1 ? 0.f : w11);

    int cy0 = min(max(y0, 0), IMH - 1), cy1 = min(max(y1, 0), IMH - 1);
    const uint32_t* r0 = g_xh2 + (((size_t)(b * 64 + cy0) * 64 + wq) << 8);
    const uint32_t* r1 = g_xh2 + (((size_t)(b * 64 + cy1) * 64 + wq) << 8);
    __half* orow = reinterpret_cast<__half*>(g_colsT4) + (size_t)n * KDIM + kk * 256;

    #pragma unroll
    for (int g = 0; g < 2; g++) {
        const int cb = g * 128 + 4 * lane;             // 4 channels per lane
        uint4 pa = *reinterpret_cast<const uint4*>(r0 + cb);
        uint4 pb = *reinterpret_cast<const uint4*>(r1 + cb);
        const uint32_t* au = &pa.x;
        const uint32_t* bu = &pb.x;
        uint32_t h[2];
        #pragma unroll
        for (int q = 0; q < 2; q++) {
            float o2[2];
            #pragma unroll
            for (int j = 0; j < 2; j++) {
                uint32_t aw = au[2 * q + j], bw = bu[2 * q + j];
                float2 fa = __half22float2(*reinterpret_cast<__half2*>(&aw));
                float2 fb = __half22float2(*reinterpret_cast<__half2*>(&bw));
                o2[j] = wl0 * fa.x + wh0 * fa.y + wl1 * fb.x + wh1 * fb.y;
            }
            __half2 hh = __floats2half2_rn(o2[0], o2[1]);
            h[q] = *reinterpret_cast<uint32_t*>(&hh);
        }
        *reinterpret_cast<uint2*>(orow + cb) = make_uint2(h[0], h[1]);
    }
}

// ---------------- Kernel 2: HMMA fp16 GEMM (R6 structure, fixed tail) ------
// CTA 64m x 128n, BK=32, 4-stage cp.async, 4 warps (warp 32m x 64n).
#define ROWB 80
#define ATILEB (64 * ROWB)
#define BTILEB (128 * ROWB)
#define STAGEB (ATILEB + BTILEB)           // 15360
#define NSTAGE 4
#define KITER (KDIM / 32)                  // 72

__global__ __launch_bounds__(128, 3) void gemm_kernel(const float* __restrict__ bias,
                                                      float* __restrict__ out) {
    extern __shared__ unsigned char smraw[];
    const uint32_t su = smem_u32(smraw);
    const int tid = threadIdx.x;
    const int wid = tid >> 5, lane = tid & 31;
    const int warp_m = wid & 1;            // 2 warps over m (32 each)
    const int warp_n = wid >> 1;           // 2 warps over n (64 each)
    const int bm = blockIdx.y * 64, bn = blockIdx.x * 128;

    const __half* gA0 = reinterpret_cast<const __half*>(g_wr4) + (size_t)bm * KDIM;
    const __half* gB0 = reinterpret_cast<const __half*>(g_colsT4) + (size_t)bn * KDIM;

    auto load_stage = [&](int it, int s) {
        uint32_t sA = su + s * STAGEB;
        uint32_t sB = sA + ATILEB;
        const __half* ga = gA0 + it * 32;
        const __half* gb = gB0 + it * 32;
        #pragma unroll
        for (int i = 0; i < 2; i++) {                 // A: 256 16B-chunks
            int idx = i * 128 + tid, row = idx >> 2, c = idx & 3;
            cp16(sA + row * ROWB + c * 16, ga + (size_t)row * KDIM + c * 8);
        }
        #pragma unroll
        for (int i = 0; i < 4; i++) {                 // B: 512 16B-chunks
            int idx = i * 128 + tid, row = idx >> 2, c = idx & 3;
            cp16(sB + row * ROWB + c * 16, gb + (size_t)row * KDIM + c * 8);
        }
        CP_COMMIT();
    };

    float acc[2][8][4];
    #pragma unroll
    for (int i = 0; i < 2; i++)
        #pragma unroll
        for (int j = 0; j < 8; j++)
            #pragma unroll
            for (int q = 0; q < 4; q++) acc[i][j][q] = 0.f;

    load_stage(0, 0);
    load_stage(1, 1);
    load_stage(2, 2);
    CP_WAIT2();
    __syncthreads();

    const uint32_t aoff = (uint32_t)(warp_m * 32 + (lane & 15)) * ROWB + ((lane >> 4) << 4);
    const uint32_t boff = (uint32_t)(warp_n * 64 + (lane & 7) + ((lane >> 4) << 3)) * ROWB +
                          (((lane >> 3) & 1) << 4);

    #pragma unroll 1
    for (int it = 0; it < KITER; it++) {
        if (it + 3 < KITER) load_stage(it + 3, (it + 3) & 3);

        const uint32_t sA = su + (it & 3) * STAGEB;
        const uint32_t sB = sA + ATILEB;
        #pragma unroll
        for (int ks = 0; ks < 2; ks++) {
            uint32_t a[2][4], b[8][2];
            #pragma unroll
            for (int mt = 0; mt < 2; mt++)
                LDSM_X4(a[mt][0], a[mt][1], a[mt][2], a[mt][3],
                        sA + aoff + mt * 16 * ROWB + ks * 32);
            #pragma unroll
            for (int q = 0; q < 4; q++)
                LDSM_X4(b[2 * q][0], b[2 * q][1], b[2 * q + 1][0], b[2 * q + 1][1],
                        sB + boff + q * 16 * ROWB + ks * 32);
            #pragma unroll
            for (int mt = 0; mt < 2; mt++)
                #pragma unroll
                for (int nt = 0; nt < 8; nt++)
                    MMA16816(acc[mt][nt], a[mt], b[nt][0], b[nt][1]);
        }
        // tail-correct drain: ensure group (it+1) is complete before next iter
        if (it < KITER - 3)      CP_WAIT2();
        else if (it == KITER - 3) CP_WAIT1();
        else                      CP_WAIT0();
        __syncthreads();
    }

    const int g = lane >> 2, t2 = (lane & 3) * 2;
    const int b_img = bn >> 12;
    const int hw0 = bn & 4095;
    #pragma unroll
    for (int mt = 0; mt < 2; mt++) {
        int m0 = bm + warp_m * 32 + mt * 16 + g;
        float bv0 = __ldg(&bias[m0]);
        float bv1 = __ldg(&bias[m0 + 8]);
        float* row0 = out + ((size_t)b_img * COUT + m0) * HW + hw0;
        float* row1 = row0 + 8 * HW;
        #pragma unroll
        for (int nt = 0; nt < 8; nt++) {
            int nc = warp_n * 64 + nt * 8 + t2;
            *reinterpret_cast<float2*>(row0 + nc) =
                make_float2(acc[mt][nt][0] + bv0, acc[mt][nt][1] + bv0);
            *reinterpret_cast<float2*>(row1 + nc) =
                make_float2(acc[mt][nt][2] + bv1, acc[mt][nt][3] + bv1);
        }
    }
}

// ---------------------------------------------------------------------------
extern "C" void kernel_launch(void* const* d_in, const int* in_sizes, int n_in,
                              void* d_out, int out_size) {
    const float* x      = (const float*)d_in[0];
    const float* offset = (const float*)d_in[1];
    const float* weight = (const float*)d_in[2];
    const float* bias   = (const float*)d_in[3];
    float* out = (float*)d_out;

    xpack_kernel<<<4 * IMH, 256>>>(x);                    // 256 blocks
    repack_kernel<<<COUT * KDIM / 512, 512>>>(weight);
    gather_kernel<<<NDIM * KKTAP / 8, 256>>>(offset);     // 18432 blocks

    cudaFuncSetAttribute(gemm_kernel, cudaFuncAttributeMaxDynamicSharedMemorySize,
                         NSTAGE * STAGEB);
    dim3 grid(NDIM / 128, COUT / 64);      // 512 CTAs
    gemm_kernel<<<grid, 128, NSTAGE * STAGEB>>>(bias, out);
}

// round 9
// speedup vs baseline: 1.4972x; 1.4972x over previous
#include <cuda_runtime.h>
#include <cuda_fp16.h>
#include <cstdint>

#define IMH 64
#define IMW 64
#define HW 4096
#define CIN 256
#define COUT 256
#define KKTAP 9
#define KDIM 2304            // k' = kk*256 + c
#define NDIM 16384

// cols_T: [NDIM][KDIM] fp16 (row = 4608 B)  — B operand, K-major
__device__ uint4 g_colsT4[(size_t)NDIM * 288];
// repacked weight: [COUT][KDIM] fp16, same k' order — A operand, K-major
__device__ uint4 g_wr4[(size_t)COUT * 288];
// NHWC parity-pair x: [b*64+row][wq][c] as half2 words.
// wq<32: pair (x[2j],x[2j+1]); wq=32+j: pair (x[2j+1],x[2j+2]) (clamped)
__device__ uint32_t g_xh2[(size_t)4 * IMH * 64 * CIN];

__device__ __forceinline__ uint32_t smem_u32(const void* p) {
    return (uint32_t)__cvta_generic_to_shared(p);
}
__device__ __forceinline__ void cp16(uint32_t d, const void* s) {
    asm volatile("cp.async.cg.shared.global [%0], [%1], 16;" :: "r"(d), "l"(s) : "memory");
}
#define CP_COMMIT() asm volatile("cp.async.commit_group;" ::: "memory")
#define CP_WAIT2()  asm volatile("cp.async.wait_group 2;" ::: "memory")

#define LDSM_X4(r0, r1, r2, r3, a)                                          \
    asm volatile("ldmatrix.sync.aligned.m8n8.x4.shared.b16 {%0,%1,%2,%3}, [%4];" \
                 : "=r"(r0), "=r"(r1), "=r"(r2), "=r"(r3) : "r"(a))

#define MMA16816(c, av, bv0, bv1)                                           \
    asm volatile("mma.sync.aligned.m16n8k16.row.col.f32.f16.f16.f32 "       \
                 "{%0,%1,%2,%3}, {%4,%5,%6,%7}, {%8,%9}, {%0,%1,%2,%3};"    \
                 : "+f"((c)[0]), "+f"((c)[1]), "+f"((c)[2]), "+f"((c)[3])   \
                 : "r"((av)[0]), "r"((av)[1]), "r"((av)[2]), "r"((av)[3]),  \
                   "r"(bv0), "r"(bv1))

// ---------------- Kernel A: x NCHW fp32 -> NHWC parity-pair fp16 -----------
__global__ __launch_bounds__(256) void xpack_kernel(const float* __restrict__ x) {
    const int blk = blockIdx.x;            // b*64 + row
    const int c = threadIdx.x;
    const float* src = x + ((size_t)(blk >> 6) * CIN + c) * HW + (blk & 63) * 64;
    float v[64];
    #pragma unroll
    for (int i = 0; i < 16; i++) {
        float4 t = reinterpret_cast<const float4*>(src)[i];
        v[4 * i] = t.x; v[4 * i + 1] = t.y; v[4 * i + 2] = t.z; v[4 * i + 3] = t.w;
    }
    uint32_t w[64];
    #pragma unroll
    for (int j = 0; j < 32; j++) {
        __half2 h = __floats2half2_rn(v[2 * j], v[2 * j + 1]);
        w[j] = *reinterpret_cast<uint32_t*>(&h);
    }
    #pragma unroll
    for (int j = 0; j < 32; j++) {
        float nx = (j == 31) ? v[63] : v[2 * j + 2];
        __half2 h = __floats2half2_rn(v[2 * j + 1], nx);
        w[32 + j] = *reinterpret_cast<uint32_t*>(&h);
    }
    uint32_t* dst = g_xh2 + (size_t)blk * 64 * 256 + c;
    #pragma unroll
    for (int q = 0; q < 64; q++) dst[q * 256] = w[q];   // coalesced across c
}

// ---------------- Kernel 0: weight repack fp32->fp16, k' = kk*256+c --------
__global__ __launch_bounds__(512) void repack_kernel(const float* __restrict__ w) {
    int idx = blockIdx.x * 512 + threadIdx.x;
    int o = idx / KDIM;
    int r = idx - o * KDIM;
    int kk = r >> 8;
    int c = r & 255;
    reinterpret_cast<__half*>(g_wr4)[idx] = __float2half(w[(o * CIN + c) * KKTAP + kk]);
}

// ---------------- Kernel 1: gather, warp = one tap, coalesced NHWC ---------
__global__ __launch_bounds__(256) void gather_kernel(const float* __restrict__ offset) {
    const int gw = (blockIdx.x * 256 + threadIdx.x) >> 5;   // tap id < 147456
    const int lane = threadIdx.x & 31;
    const int n = gw / 9;
    const int kk = gw - n * 9;
    const int b = n >> 12, hw = n & 4095, ho = hw >> 6, wo = hw & 63;

    const float* offb = offset + (size_t)b * (2 * KKTAP) * HW;
    float offy = offb[(2 * kk) * HW + hw];                  // warp-broadcast
    float offx = offb[(2 * kk + 1) * HW + hw];
    float py = (float)(ho - 1 + kk / 3) + offy;
    float px = (float)(wo - 1 + kk % 3) + offx;

    float fy = floorf(py), fx = floorf(px);
    float ly = py - fy, lx = px - fx;
    int y0 = (int)fy, x0 = (int)fx, y1 = y0 + 1, x1 = x0 + 1;
    bool vy0 = (y0 >= 0) & (y0 < IMH), vy1 = (y1 >= 0) & (y1 < IMH);
    bool vx0 = (x0 >= 0) & (x0 < IMW), vx1 = (x1 >= 0) & (x1 < IMW);
    float w00 = (1.f - ly) * (1.f - lx) * (float)(vy0 & vx0);
    float w01 = (1.f - ly) * lx * (float)(vy0 & vx1);
    float w10 = ly * (1.f - lx) * (float)(vy1 & vx0);
    float w11 = ly * lx * (float)(vy1 & vx1);

    int qx = min(max(x0, 0), 62);
    int wq = (qx & 1) ? (32 + (qx >> 1)) : (qx >> 1);
    bool sel0 = (x0 == qx);
    bool sel1 = (x1 == qx);
    float wl0 = (sel0 ? w00 : 0.f) + (sel1 ? w01 : 0.f);
    float wh0 = (sel0 ? 0.f : w00) + (sel1 ? 0.f : w01);
    float wl1 = (sel0 ? w10 : 0.f) + (sel1 ? w11 : 0.f);
    float wh1 = (sel0 ? 0.f : w10) + (sel1 ? 0.f : w11);

    int cy0 = min(max(y0, 0), IMH - 1), cy1 = min(max(y1, 0), IMH - 1);
    const uint32_t* r0 = g_xh2 + (((size_t)(b * 64 + cy0) * 64 + wq) << 8);
    const uint32_t* r1 = g_xh2 + (((size_t)(b * 64 + cy1) * 64 + wq) << 8);
    __half* orow = reinterpret_cast<__half*>(g_colsT4) + (size_t)n * KDIM + kk * 256;

    #pragma unroll
    for (int g = 0; g < 2; g++) {
        const int cb = g * 128 + 4 * lane;             // 4 channels per lane
        uint4 pa = *reinterpret_cast<const uint4*>(r0 + cb);
        uint4 pb = *reinterpret_cast<const uint4*>(r1 + cb);
        const uint32_t* au = &pa.x;
        const uint32_t* bu = &pb.x;
        uint32_t h[2];
        #pragma unroll
        for (int q = 0; q < 2; q++) {
            float o2[2];
            #pragma unroll
            for (int j = 0; j < 2; j++) {
                uint32_t aw = au[2 * q + j], bw = bu[2 * q + j];
                float2 fa = __half22float2(*reinterpret_cast<__half2*>(&aw));
                float2 fb = __half22float2(*reinterpret_cast<__half2*>(&bw));
                o2[j] = wl0 * fa.x + wh0 * fa.y + wl1 * fb.x + wh1 * fb.y;
            }
            __half2 hh = __floats2half2_rn(o2[0], o2[1]);
            h[q] = *reinterpret_cast<uint32_t*>(&hh);
        }
        *reinterpret_cast<uint2*>(orow + cb) = make_uint2(h[0], h[1]);
    }
}

// ---------------- Kernel 2: HMMA fp16 GEMM — exact R6 loop shape -----------
// CTA 64m x 128n, BK=32, 4-stage cp.async, 4 warps (warp 32m x 64n).
// Tail: empty commit_group keeps group accounting uniform -> CP_WAIT2 is
// always sufficient AND branch-free (compiler free to unroll+pipeline).
#define ROWB 80
#define ATILEB (64 * ROWB)
#define BTILEB (128 * ROWB)
#define STAGEB (ATILEB + BTILEB)           // 15360
#define NSTAGE 4
#define KITER (KDIM / 32)                  // 72

__global__ __launch_bounds__(128, 3) void gemm_kernel(const float* __restrict__ bias,
                                                      float* __restrict__ out) {
    extern __shared__ unsigned char smraw[];
    const uint32_t su = smem_u32(smraw);
    const int tid = threadIdx.x;
    const int wid = tid >> 5, lane = tid & 31;
    const int warp_m = wid & 1;            // 2 warps over m (32 each)
    const int warp_n = wid >> 1;           // 2 warps over n (64 each)
    const int bm = blockIdx.y * 64, bn = blockIdx.x * 128;

    const __half* gA0 = reinterpret_cast<const __half*>(g_wr4) + (size_t)bm * KDIM;
    const __half* gB0 = reinterpret_cast<const __half*>(g_colsT4) + (size_t)bn * KDIM;

    auto load_stage = [&](int it, int s) {
        uint32_t sA = su + s * STAGEB;
        uint32_t sB = sA + ATILEB;
        const __half* ga = gA0 + it * 32;
        const __half* gb = gB0 + it * 32;
        #pragma unroll
        for (int i = 0; i < 2; i++) {                 // A: 256 16B-chunks
            int idx = i * 128 + tid, row = idx >> 2, c = idx & 3;
            cp16(sA + row * ROWB + c * 16, ga + (size_t)row * KDIM + c * 8);
        }
        #pragma unroll
        for (int i = 0; i < 4; i++) {                 // B: 512 16B-chunks
            int idx = i * 128 + tid, row = idx >> 2, c = idx & 3;
            cp16(sB + row * ROWB + c * 16, gb + (size_t)row * KDIM + c * 8);
        }
        CP_COMMIT();
    };

    float acc[2][8][4];
    #pragma unroll
    for (int i = 0; i < 2; i++)
        #pragma unroll
        for (int j = 0; j < 8; j++)
            #pragma unroll
            for (int q = 0; q < 4; q++) acc[i][j][q] = 0.f;

    load_stage(0, 0);
    load_stage(1, 1);
    load_stage(2, 2);
    CP_WAIT2();
    __syncthreads();

    const uint32_t aoff = (uint32_t)(warp_m * 32 + (lane & 15)) * ROWB + ((lane >> 4) << 4);
    const uint32_t boff = (uint32_t)(warp_n * 64 + (lane & 7) + ((lane >> 4) << 3)) * ROWB +
                          (((lane >> 3) & 1) << 4);

    for (int it = 0; it < KITER; it++) {
        if (it + 3 < KITER) load_stage(it + 3, (it + 3) & 3);
        else                CP_COMMIT();              // empty group, keeps WAIT2 exact

        const uint32_t sA = su + (it & 3) * STAGEB;
        const uint32_t sB = sA + ATILEB;
        #pragma unroll
        for (int ks = 0; ks < 2; ks++) {
            uint32_t a[2][4], b[8][2];
            #pragma unroll
            for (int mt = 0; mt < 2; mt++)
                LDSM_X4(a[mt][0], a[mt][1], a[mt][2], a[mt][3],
                        sA + aoff + mt * 16 * ROWB + ks * 32);
            #pragma unroll
            for (int q = 0; q < 4; q++)
                LDSM_X4(b[2 * q][0], b[2 * q][1], b[2 * q + 1][0], b[2 * q + 1][1],
                        sB + boff + q * 16 * ROWB + ks * 32);
            #pragma unroll
            for (int mt = 0; mt < 2; mt++)
                #pragma unroll
                for (int nt = 0; nt < 8; nt++)
                    MMA16816(acc[mt][nt], a[mt], b[nt][0], b[nt][1]);
        }
        CP_WAIT2();
        __syncthreads();
    }

    const int g = lane >> 2, t2 = (lane & 3) * 2;
    const int b_img = bn >> 12;
    const int hw0 = bn & 4095;
    #pragma unroll
    for (int mt = 0; mt < 2; mt++) {
        int m0 = bm + warp_m * 32 + mt * 16 + g;
        float bv0 = __ldg(&bias[m0]);
        float bv1 = __ldg(&bias[m0 + 8]);
        float* row0 = out + ((size_t)b_img * COUT + m0) * HW + hw0;
        float* row1 = row0 + 8 * HW;
        #pragma unroll
        for (int nt = 0; nt < 8; nt++) {
            int nc = warp_n * 64 + nt * 8 + t2;
            *reinterpret_cast<float2*>(row0 + nc) =
                make_float2(acc[mt][nt][0] + bv0, acc[mt][nt][1] + bv0);
            *reinterpret_cast<float2*>(row1 + nc) =
                make_float2(acc[mt][nt][2] + bv1, acc[mt][nt][3] + bv1);
        }
    }
}

// ---------------------------------------------------------------------------
extern "C" void kernel_launch(void* const* d_in, const int* in_sizes, int n_in,
                              void* d_out, int out_size) {
    const float* x      = (const float*)d_in[0];
    const float* offset = (const float*)d_in[1];
    const float* weight = (const float*)d_in[2];
    const float* bias   = (const float*)d_in[3];
    float* out = (float*)d_out;

    xpack_kernel<<<4 * IMH, 256>>>(x);                    // 256 blocks
    repack_kernel<<<COUT * KDIM / 512, 512>>>(weight);
    gather_kernel<<<NDIM * KKTAP / 8, 256>>>(offset);     // 18432 blocks

    cudaFuncSetAttribute(gemm_kernel, cudaFuncAttributeMaxDynamicSharedMemorySize,
                         NSTAGE * STAGEB);
    dim3 grid(NDIM / 128, COUT / 64);      // 512 CTAs
    gemm_kernel<<<grid, 128, NSTAGE * STAGEB>>>(bias, out);
}

// round 11
// speedup vs baseline: 1.6190x; 1.0814x over previous
#include <cuda_runtime.h>
#include <cuda_fp16.h>
#include <cstdint>

#define IMH 64
#define IMW 64
#define HW 4096
#define CIN 256
#define COUT 256
#define KKTAP 9
#define KDIM 2304            // k' = kk*256 + c
#define NDIM 16384

// cols_T: [NDIM][KDIM] fp16 (row = 4608 B)  — B operand, K-major
__device__ uint4 g_colsT4[(size_t)NDIM * 288];
// repacked weight: [COUT][KDIM] fp16, same k' order — A operand, K-major
__device__ uint4 g_wr4[(size_t)COUT * 288];
// NHWC parity-pair x: [b*64+row][wq][c] as half2 words.
__device__ uint32_t g_xh2[(size_t)4 * IMH * 64 * CIN];

__device__ __forceinline__ uint32_t smem_u32(const void* p) {
    return (uint32_t)__cvta_generic_to_shared(p);
}
__device__ __forceinline__ void cp16(uint32_t d, const void* s) {
    asm volatile("cp.async.cg.shared.global [%0], [%1], 16;" :: "r"(d), "l"(s) : "memory");
}
#define CP_COMMIT() asm volatile("cp.async.commit_group;" ::: "memory")
#define CP_WAIT1()  asm volatile("cp.async.wait_group 1;" ::: "memory")

#define LDSM_X4(r0, r1, r2, r3, a)                                          \
    asm volatile("ldmatrix.sync.aligned.m8n8.x4.shared.b16 {%0,%1,%2,%3}, [%4];" \
                 : "=r"(r0), "=r"(r1), "=r"(r2), "=r"(r3) : "r"(a))

#define MMA16816(c, av, bv0, bv1)                                           \
    asm volatile("mma.sync.aligned.m16n8k16.row.col.f32.f16.f16.f32 "       \
                 "{%0,%1,%2,%3}, {%4,%5,%6,%7}, {%8,%9}, {%0,%1,%2,%3};"    \
                 : "+f"((c)[0]), "+f"((c)[1]), "+f"((c)[2]), "+f"((c)[3])   \
                 : "r"((av)[0]), "r"((av)[1]), "r"((av)[2]), "r"((av)[3]),  \
                   "r"(bv0), "r"(bv1))

// ---------------- Kernel A: x NCHW fp32 -> NHWC parity-pair fp16 -----------
__global__ __launch_bounds__(256) void xpack_kernel(const float* __restrict__ x) {
    const int blk = blockIdx.x;            // b*64 + row
    const int c = threadIdx.x;
    const float* src = x + ((size_t)(blk >> 6) * CIN + c) * HW + (blk & 63) * 64;
    float v[64];
    #pragma unroll
    for (int i = 0; i < 16; i++) {
        float4 t = reinterpret_cast<const float4*>(src)[i];
        v[4 * i] = t.x; v[4 * i + 1] = t.y; v[4 * i + 2] = t.z; v[4 * i + 3] = t.w;
    }
    uint32_t w[64];
    #pragma unroll
    for (int j = 0; j < 32; j++) {
        __half2 h = __floats2half2_rn(v[2 * j], v[2 * j + 1]);
        w[j] = *reinterpret_cast<uint32_t*>(&h);
    }
    #pragma unroll
    for (int j = 0; j < 32; j++) {
        float nx = (j == 31) ? v[63] : v[2 * j + 2];
        __half2 h = __floats2half2_rn(v[2 * j + 1], nx);
        w[32 + j] = *reinterpret_cast<uint32_t*>(&h);
    }
    uint32_t* dst = g_xh2 + (size_t)blk * 64 * 256 + c;
    #pragma unroll
    for (int q = 0; q < 64; q++) dst[q * 256] = w[q];   // coalesced across c
}

// ---------------- Kernel 0: weight repack fp32->fp16, k' = kk*256+c --------
__global__ __launch_bounds__(512) void repack_kernel(const float* __restrict__ w) {
    int idx = blockIdx.x * 512 + threadIdx.x;
    int o = idx / KDIM;
    int r = idx - o * KDIM;
    int kk = r >> 8;
    int c = r & 255;
    reinterpret_cast<__half*>(g_wr4)[idx] = __float2half(w[(o * CIN + c) * KKTAP + kk]);
}

// ---------------- Kernel 1: gather, warp = one tap, coalesced NHWC ---------
__global__ __launch_bounds__(256) void gather_kernel(const float* __restrict__ offset) {
    const int gw = (blockIdx.x * 256 + threadIdx.x) >> 5;   // tap id < 147456
    const int lane = threadIdx.x & 31;
    const int n = gw / 9;
    const int kk = gw - n * 9;
    const int b = n >> 12, hw = n & 4095, ho = hw >> 6, wo = hw & 63;

    const float* offb = offset + (size_t)b * (2 * KKTAP) * HW;
    float offy = offb[(2 * kk) * HW + hw];                  // warp-broadcast
    float offx = offb[(2 * kk + 1) * HW + hw];
    float py = (float)(ho - 1 + kk / 3) + offy;
    float px = (float)(wo - 1 + kk % 3) + offx;

    float fy = floorf(py), fx = floorf(px);
    float ly = py - fy, lx = px - fx;
    int y0 = (int)fy, x0 = (int)fx, y1 = y0 + 1, x1 = x0 + 1;
    bool vy0 = (y0 >= 0) & (y0 < IMH), vy1 = (y1 >= 0) & (y1 < IMH);
    bool vx0 = (x0 >= 0) & (x0 < IMW), vx1 = (x1 >= 0) & (x1 < IMW);
    float w00 = (1.f - ly) * (1.f - lx) * (float)(vy0 & vx0);
    float w01 = (1.f - ly) * lx * (float)(vy0 & vx1);
    float w10 = ly * (1.f - lx) * (float)(vy1 & vx0);
    float w11 = ly * lx * (float)(vy1 & vx1);

    int qx = min(max(x0, 0), 62);
    int wq = (qx & 1) ? (32 + (qx >> 1)) : (qx >> 1);
    bool sel0 = (x0 == qx);
    bool sel1 = (x1 == qx);
    float wl0 = (sel0 ? w00 : 0.f) + (sel1 ? w01 : 0.f);
    float wh0 = (sel0 ? 0.f : w00) + (sel1 ? 0.f : w01);
    float wl1 = (sel0 ? w10 : 0.f) + (sel1 ? w11 : 0.f);
    float wh1 = (sel0 ? 0.f : w10) + (sel1 ? 0.f : w11);

    int cy0 = min(max(y0, 0), IMH - 1), cy1 = min(max(y1, 0), IMH - 1);
    const uint32_t* r0 = g_xh2 + (((size_t)(b * 64 + cy0) * 64 + wq) << 8);
    const uint32_t* r1 = g_xh2 + (((size_t)(b * 64 + cy1) * 64 + wq) << 8);
    __half* orow = reinterpret_cast<__half*>(g_colsT4) + (size_t)n * KDIM + kk * 256;

    #pragma unroll
    for (int g = 0; g < 2; g++) {
        const int cb = g * 128 + 4 * lane;             // 4 channels per lane
        uint4 pa = *reinterpret_cast<const uint4*>(r0 + cb);
        uint4 pb = *reinterpret_cast<const uint4*>(r1 + cb);
        const uint32_t* au = &pa.x;
        const uint32_t* bu = &pb.x;
        uint32_t h[2];
        #pragma unroll
        for (int q = 0; q < 2; q++) {
            float o2[2];
            #pragma unroll
            for (int j = 0; j < 2; j++) {
                uint32_t aw = au[2 * q + j], bw = bu[2 * q + j];
                float2 fa = __half22float2(*reinterpret_cast<__half2*>(&aw));
                float2 fb = __half22float2(*reinterpret_cast<__half2*>(&bw));
                o2[j] = wl0 * fa.x + wh0 * fa.y + wl1 * fb.x + wh1 * fb.y;
            }
            __half2 hh = __floats2half2_rn(o2[0], o2[1]);
            h[q] = *reinterpret_cast<uint32_t*>(&hh);
        }
        *reinterpret_cast<uint2*>(orow + cb) = make_uint2(h[0], h[1]);
    }
}

// ---------------- Kernel 2: HMMA fp16 GEMM, BK=64, 3 stages ----------------
// CTA 64m x 128n, 4 warps (warp 32m x 64n). 36 iterations, one barrier each.
// Prefetch distance 2 with 3 stages => the wait must drain everything except
// the newest group: cp.async.wait_group 1. One group per iteration (empty
// commits at the tail) keeps accounting uniform & branch-free.
#define ROWB 176                           // 64 K-halfs = 128B data + 48 pad
#define ATILEB (64 * ROWB)                 // 11264
#define BTILEB (128 * ROWB)                // 22528
#define STAGEB (ATILEB + BTILEB)           // 33792
#define NSTAGE 3
#define KITER (KDIM / 64)                  // 36

__global__ __launch_bounds__(128, 2) void gemm_kernel(const float* __restrict__ bias,
                                                      float* __restrict__ out) {
    extern __shared__ unsigned char smraw[];
    const uint32_t su = smem_u32(smraw);
    const int tid = threadIdx.x;
    const int wid = tid >> 5, lane = tid & 31;
    const int warp_m = wid & 1;            // 2 warps over m (32 each)
    const int warp_n = wid >> 1;           // 2 warps over n (64 each)
    const int bm = blockIdx.y * 64, bn = blockIdx.x * 128;

    const __half* gA0 = reinterpret_cast<const __half*>(g_wr4) + (size_t)bm * KDIM;
    const __half* gB0 = reinterpret_cast<const __half*>(g_colsT4) + (size_t)bn * KDIM;

    auto load_stage = [&](int it, int s) {
        uint32_t sA = su + s * STAGEB;
        uint32_t sB = sA + ATILEB;
        const __half* ga = gA0 + it * 64;
        const __half* gb = gB0 + it * 64;
        #pragma unroll
        for (int i = 0; i < 4; i++) {                 // A: 512 16B-chunks
            int idx = i * 128 + tid, row = idx >> 3, c = idx & 7;
            cp16(sA + row * ROWB + c * 16, ga + (size_t)row * KDIM + c * 8);
        }
        #pragma unroll
        for (int i = 0; i < 8; i++) {                 // B: 1024 16B-chunks
            int idx = i * 128 + tid, row = idx >> 3, c = idx & 7;
            cp16(sB + row * ROWB + c * 16, gb + (size_t)row * KDIM + c * 8);
        }
        CP_COMMIT();
    };

    float acc[2][8][4];
    #pragma unroll
    for (int i = 0; i < 2; i++)
        #pragma unroll
        for (int j = 0; j < 8; j++)
            #pragma unroll
            for (int q = 0; q < 4; q++) acc[i][j][q] = 0.f;

    load_stage(0, 0);
    load_stage(1, 1);
    CP_WAIT1();                            // stage 0 landed, stage 1 in flight
    __syncthreads();

    const uint32_t aoff = (uint32_t)(warp_m * 32 + (lane & 15)) * ROWB + ((lane >> 4) << 4);
    const uint32_t boff = (uint32_t)(warp_n * 64 + (lane & 7) + ((lane >> 4) << 3)) * ROWB +
                          (((lane >> 3) & 1) << 4);

    for (int it = 0; it < KITER; it++) {
        if (it + 2 < KITER) load_stage(it + 2, (it + 2) % NSTAGE);
        else                CP_COMMIT();   // empty group, keeps WAIT1 exact

        const uint32_t sA = su + (it % NSTAGE) * STAGEB;
        const uint32_t sB = sA + ATILEB;
        #pragma unroll
        for (int ks = 0; ks < 4; ks++) {
            uint32_t a[2][4], b[8][2];
            #pragma unroll
            for (int mt = 0; mt < 2; mt++)
                LDSM_X4(a[mt][0], a[mt][1], a[mt][2], a[mt][3],
                        sA + aoff + mt * 16 * ROWB + ks * 32);
            #pragma unroll
            for (int q = 0; q < 4; q++)
                LDSM_X4(b[2 * q][0], b[2 * q][1], b[2 * q + 1][0], b[2 * q + 1][1],
                        sB + boff + q * 16 * ROWB + ks * 32);
            #pragma unroll
            for (int mt = 0; mt < 2; mt++)
                #pragma unroll
                for (int nt = 0; nt < 8; nt++)
                    MMA16816(acc[mt][nt], a[mt], b[nt][0], b[nt][1]);
        }
        CP_WAIT1();                        // stage it+1 landed before next iter
        __syncthreads();
    }

    const int g = lane >> 2, t2 = (lane & 3) * 2;
    const int b_img = bn >> 12;
    const int hw0 = bn & 4095;
    #pragma unroll
    for (int mt = 0; mt < 2; mt++) {
        int m0 = bm + warp_m * 32 + mt * 16 + g;
        float bv0 = __ldg(&bias[m0]);
        float bv1 = __ldg(&bias[m0 + 8]);
        float* row0 = out + ((size_t)b_img * COUT + m0) * HW + hw0;
        float* row1 = row0 + 8 * HW;
        #pragma unroll
        for (int nt = 0; nt < 8; nt++) {
            int nc = warp_n * 64 + nt * 8 + t2;
            *reinterpret_cast<float2*>(row0 + nc) =
                make_float2(acc[mt][nt][0] + bv0, acc[mt][nt][1] + bv0);
            *reinterpret_cast<float2*>(row1 + nc) =
                make_float2(acc[mt][nt][2] + bv1, acc[mt][nt][3] + bv1);
        }
    }
}

// ---------------------------------------------------------------------------
extern "C" void kernel_launch(void* const* d_in, const int* in_sizes, int n_in,
                              void* d_out, int out_size) {
    const float* x      = (const float*)d_in[0];
    const float* offset = (const float*)d_in[1];
    const float* weight = (const float*)d_in[2];
    const float* bias   = (const float*)d_in[3];
    float* out = (float*)d_out;

    xpack_kernel<<<4 * IMH, 256>>>(x);                    // 256 blocks
    repack_kernel<<<COUT * KDIM / 512, 512>>>(weight);
    gather_kernel<<<NDIM * KKTAP / 8, 256>>>(offset);     // 18432 blocks

    cudaFuncSetAttribute(gemm_kernel, cudaFuncAttributeMaxDynamicSharedMemorySize,
                         NSTAGE * STAGEB);
    dim3 grid(NDIM / 128, COUT / 64);      // 512 CTAs
    gemm_kernel<<<grid, 128, NSTAGE * STAGEB>>>(bias, out);
}

// round 12
// speedup vs baseline: 1.7145x; 1.0589x over previous
#include <cuda_runtime.h>
#include <cuda_fp16.h>
#include <cstdint>

#define IMH 64
#define IMW 64
#define HW 4096
#define CIN 256
#define COUT 256
#define KKTAP 9
#define KDIM 2304            // k' = kk*256 + c
#define NDIM 16384

// cols_T: [NDIM][KDIM] fp16 (row = 4608 B)  — B operand, K-major
__device__ uint4 g_colsT4[(size_t)NDIM * 288];
// repacked weight: [COUT][KDIM] fp16, same k' order — A operand, K-major
__device__ uint4 g_wr4[(size_t)COUT * 288];
// NHWC parity-pair x: [b*64+row][wq][c] as half2 words.
__device__ uint32_t g_xh2[(size_t)4 * IMH * 64 * CIN];

__device__ __forceinline__ uint32_t smem_u32(const void* p) {
    return (uint32_t)__cvta_generic_to_shared(p);
}
__device__ __forceinline__ void cp16(uint32_t d, const void* s) {
    asm volatile("cp.async.cg.shared.global [%0], [%1], 16;" :: "r"(d), "l"(s) : "memory");
}
#define CP_COMMIT() asm volatile("cp.async.commit_group;" ::: "memory")
#define CP_WAIT0()  asm volatile("cp.async.wait_group 0;" ::: "memory")

#define LDSM_X4(r0, r1, r2, r3, a)                                          \
    asm volatile("ldmatrix.sync.aligned.m8n8.x4.shared.b16 {%0,%1,%2,%3}, [%4];" \
                 : "=r"(r0), "=r"(r1), "=r"(r2), "=r"(r3) : "r"(a))

#define MMA16816(c, av, bv0, bv1)                                           \
    asm volatile("mma.sync.aligned.m16n8k16.row.col.f32.f16.f16.f32 "       \
                 "{%0,%1,%2,%3}, {%4,%5,%6,%7}, {%8,%9}, {%0,%1,%2,%3};"    \
                 : "+f"((c)[0]), "+f"((c)[1]), "+f"((c)[2]), "+f"((c)[3])   \
                 : "r"((av)[0]), "r"((av)[1]), "r"((av)[2]), "r"((av)[3]),  \
                   "r"(bv0), "r"(bv1))

// ---------------- Kernel A: x NCHW fp32 -> NHWC parity-pair fp16 -----------
__global__ __launch_bounds__(256) void xpack_kernel(const float* __restrict__ x) {
    const int blk = blockIdx.x;            // b*64 + row
    const int c = threadIdx.x;
    const float* src = x + ((size_t)(blk >> 6) * CIN + c) * HW + (blk & 63) * 64;
    float v[64];
    #pragma unroll
    for (int i = 0; i < 16; i++) {
        float4 t = reinterpret_cast<const float4*>(src)[i];
        v[4 * i] = t.x; v[4 * i + 1] = t.y; v[4 * i + 2] = t.z; v[4 * i + 3] = t.w;
    }
    uint32_t w[64];
    #pragma unroll
    for (int j = 0; j < 32; j++) {
        __half2 h = __floats2half2_rn(v[2 * j], v[2 * j + 1]);
        w[j] = *reinterpret_cast<uint32_t*>(&h);
    }
    #pragma unroll
    for (int j = 0; j < 32; j++) {
        float nx = (j == 31) ? v[63] : v[2 * j + 2];
        __half2 h = __floats2half2_rn(v[2 * j + 1], nx);
        w[32 + j] = *reinterpret_cast<uint32_t*>(&h);
    }
    uint32_t* dst = g_xh2 + (size_t)blk * 64 * 256 + c;
    #pragma unroll
    for (int q = 0; q < 64; q++) dst[q * 256] = w[q];   // coalesced across c
}

// ---------------- Kernel 0: weight repack fp32->fp16, k' = kk*256+c --------
__global__ __launch_bounds__(512) void repack_kernel(const float* __restrict__ w) {
    int idx = blockIdx.x * 512 + threadIdx.x;
    int o = idx / KDIM;
    int r = idx - o * KDIM;
    int kk = r >> 8;
    int c = r & 255;
    reinterpret_cast<__half*>(g_wr4)[idx] = __float2half(w[(o * CIN + c) * KKTAP + kk]);
}

// ---------------- Kernel 1: gather, warp = one tap, coalesced NHWC ---------
__global__ __launch_bounds__(256) void gather_kernel(const float* __restrict__ offset) {
    const int gw = (blockIdx.x * 256 + threadIdx.x) >> 5;   // tap id < 147456
    const int lane = threadIdx.x & 31;
    const int n = gw / 9;
    const int kk = gw - n * 9;
    const int b = n >> 12, hw = n & 4095, ho = hw >> 6, wo = hw & 63;

    const float* offb = offset + (size_t)b * (2 * KKTAP) * HW;
    float offy = offb[(2 * kk) * HW + hw];                  // warp-broadcast
    float offx = offb[(2 * kk + 1) * HW + hw];
    float py = (float)(ho - 1 + kk / 3) + offy;
    float px = (float)(wo - 1 + kk % 3) + offx;

    float fy = floorf(py), fx = floorf(px);
    float ly = py - fy, lx = px - fx;
    int y0 = (int)fy, x0 = (int)fx, y1 = y0 + 1, x1 = x0 + 1;
    bool vy0 = (y0 >= 0) & (y0 < IMH), vy1 = (y1 >= 0) & (y1 < IMH);
    bool vx0 = (x0 >= 0) & (x0 < IMW), vx1 = (x1 >= 0) & (x1 < IMW);
    float w00 = (1.f - ly) * (1.f - lx) * (float)(vy0 & vx0);
    float w01 = (1.f - ly) * lx * (float)(vy0 & vx1);
    float w10 = ly * (1.f - lx) * (float)(vy1 & vx0);
    float w11 = ly * lx * (float)(vy1 & vx1);

    int qx = min(max(x0, 0), 62);
    int wq = (qx & 1) ? (32 + (qx >> 1)) : (qx >> 1);
    bool sel0 = (x0 == qx);
    bool sel1 = (x1 == qx);
    float wl0 = (sel0 ? w00 : 0.f) + (sel1 ? w01 : 0.f);
    float wh0 = (sel0 ? 0.f : w00) + (sel1 ? 0.f : w01);
    float wl1 = (sel0 ? w10 : 0.f) + (sel1 ? w11 : 0.f);
    float wh1 = (sel0 ? 0.f : w10) + (sel1 ? 0.f : w11);

    int cy0 = min(max(y0, 0), IMH - 1), cy1 = min(max(y1, 0), IMH - 1);
    const uint32_t* r0 = g_xh2 + (((size_t)(b * 64 + cy0) * 64 + wq) << 8);
    const uint32_t* r1 = g_xh2 + (((size_t)(b * 64 + cy1) * 64 + wq) << 8);
    __half* orow = reinterpret_cast<__half*>(g_colsT4) + (size_t)n * KDIM + kk * 256;

    #pragma unroll
    for (int g = 0; g < 2; g++) {
        const int cb = g * 128 + 4 * lane;             // 4 channels per lane
        uint4 pa = *reinterpret_cast<const uint4*>(r0 + cb);
        uint4 pb = *reinterpret_cast<const uint4*>(r1 + cb);
        const uint32_t* au = &pa.x;
        const uint32_t* bu = &pb.x;
        uint32_t h[2];
        #pragma unroll
        for (int q = 0; q < 2; q++) {
            float o2[2];
            #pragma unroll
            for (int j = 0; j < 2; j++) {
                uint32_t aw = au[2 * q + j], bw = bu[2 * q + j];
                float2 fa = __half22float2(*reinterpret_cast<__half2*>(&aw));
                float2 fb = __half22float2(*reinterpret_cast<__half2*>(&bw));
                o2[j] = wl0 * fa.x + wh0 * fa.y + wl1 * fb.x + wh1 * fb.y;
            }
            __half2 hh = __floats2half2_rn(o2[0], o2[1]);
            h[q] = *reinterpret_cast<uint32_t*>(&hh);
        }
        *reinterpret_cast<uint2*>(orow + cb) = make_uint2(h[0], h[1]);
    }
}

// ---------------- Kernel 2: HMMA fp16 GEMM, 128x128, BK=64, 2 stages -------
// 8 warps (warp 32m x 64n), 256 CTAs = single wave at 2 CTAs/SM.
// Distance-1 prefetch: issue load(it+1), compute it, wait_group 0 + sync.
// One commit per iteration (empty at tail) keeps the loop branch-free.
#define ROWB 176                           // 64 K-halfs = 128B data + 48 pad
#define ATILEB (128 * ROWB)                // 22528
#define BTILEB (128 * ROWB)                // 22528
#define STAGEB (ATILEB + BTILEB)           // 45056
#define NSTAGE 2
#define KITER (KDIM / 64)                  // 36

__global__ __launch_bounds__(256, 2) void gemm_kernel(const float* __restrict__ bias,
                                                      float* __restrict__ out) {
    extern __shared__ unsigned char smraw[];
    const uint32_t su = smem_u32(smraw);
    const int tid = threadIdx.x;
    const int wid = tid >> 5, lane = tid & 31;
    const int warp_m = wid & 3;            // 4 warps over m (32 each)
    const int warp_n = wid >> 2;           // 2 warps over n (64 each)
    const int bm = blockIdx.y * 128, bn = blockIdx.x * 128;

    const __half* gA0 = reinterpret_cast<const __half*>(g_wr4) + (size_t)bm * KDIM;
    const __half* gB0 = reinterpret_cast<const __half*>(g_colsT4) + (size_t)bn * KDIM;

    auto load_stage = [&](int it, int s) {
        uint32_t sA = su + s * STAGEB;
        uint32_t sB = sA + ATILEB;
        const __half* ga = gA0 + it * 64;
        const __half* gb = gB0 + it * 64;
        #pragma unroll
        for (int i = 0; i < 4; i++) {                 // A: 1024 16B-chunks
            int idx = i * 256 + tid, row = idx >> 3, c = idx & 7;
            cp16(sA + row * ROWB + c * 16, ga + (size_t)row * KDIM + c * 8);
        }
        #pragma unroll
        for (int i = 0; i < 4; i++) {                 // B: 1024 16B-chunks
            int idx = i * 256 + tid, row = idx >> 3, c = idx & 7;
            cp16(sB + row * ROWB + c * 16, gb + (size_t)row * KDIM + c * 8);
        }
        CP_COMMIT();
    };

    float acc[2][8][4];
    #pragma unroll
    for (int i = 0; i < 2; i++)
        #pragma unroll
        for (int j = 0; j < 8; j++)
            #pragma unroll
            for (int q = 0; q < 4; q++) acc[i][j][q] = 0.f;

    load_stage(0, 0);
    CP_WAIT0();
    __syncthreads();

    const uint32_t aoff = (uint32_t)(warp_m * 32 + (lane & 15)) * ROWB + ((lane >> 4) << 4);
    const uint32_t boff = (uint32_t)(warp_n * 64 + (lane & 7) + ((lane >> 4) << 3)) * ROWB +
                          (((lane >> 3) & 1) << 4);

    for (int it = 0; it < KITER; it++) {
        if (it + 1 < KITER) load_stage(it + 1, (it + 1) & 1);
        else                CP_COMMIT();   // empty group, keeps WAIT0 uniform

        const uint32_t sA = su + (it & 1) * STAGEB;
        const uint32_t sB = sA + ATILEB;
        #pragma unroll
        for (int ks = 0; ks < 4; ks++) {
            uint32_t a[2][4], b[8][2];
            #pragma unroll
            for (int mt = 0; mt < 2; mt++)
                LDSM_X4(a[mt][0], a[mt][1], a[mt][2], a[mt][3],
                        sA + aoff + mt * 16 * ROWB + ks * 32);
            #pragma unroll
            for (int q = 0; q < 4; q++)
                LDSM_X4(b[2 * q][0], b[2 * q][1], b[2 * q + 1][0], b[2 * q + 1][1],
                        sB + boff + q * 16 * ROWB + ks * 32);
            #pragma unroll
            for (int mt = 0; mt < 2; mt++)
                #pragma unroll
                for (int nt = 0; nt < 8; nt++)
                    MMA16816(acc[mt][nt], a[mt], b[nt][0], b[nt][1]);
        }
        CP_WAIT0();                        // stage it+1 landed before next iter
        __syncthreads();
    }

    const int g = lane >> 2, t2 = (lane & 3) * 2;
    const int b_img = bn >> 12;
    const int hw0 = bn & 4095;
    #pragma unroll
    for (int mt = 0; mt < 2; mt++) {
        int m0 = bm + warp_m * 32 + mt * 16 + g;
        float bv0 = __ldg(&bias[m0]);
        float bv1 = __ldg(&bias[m0 + 8]);
        float* row0 = out + ((size_t)b_img * COUT + m0) * HW + hw0;
        float* row1 = row0 + 8 * HW;
        #pragma unroll
        for (int nt = 0; nt < 8; nt++) {
            int nc = warp_n * 64 + nt * 8 + t2;
            *reinterpret_cast<float2*>(row0 + nc) =
                make_float2(acc[mt][nt][0] + bv0, acc[mt][nt][1] + bv0);
            *reinterpret_cast<float2*>(row1 + nc) =
                make_float2(acc[mt][nt][2] + bv1, acc[mt][nt][3] + bv1);
        }
    }
}

// ---------------------------------------------------------------------------
extern "C" void kernel_launch(void* const* d_in, const int* in_sizes, int n_in,
                              void* d_out, int out_size) {
    const float* x      = (const float*)d_in[0];
    const float* offset = (const float*)d_in[1];
    const float* weight = (const float*)d_in[2];
    const float* bias   = (const float*)d_in[3];
    float* out = (float*)d_out;

    xpack_kernel<<<4 * IMH, 256>>>(x);                    // 256 blocks
    repack_kernel<<<COUT * KDIM / 512, 512>>>(weight);
    gather_kernel<<<NDIM * KKTAP / 8, 256>>>(offset);     // 18432 blocks

    cudaFuncSetAttribute(gemm_kernel, cudaFuncAttributeMaxDynamicSharedMemorySize,
                         NSTAGE * STAGEB);
    dim3 grid(NDIM / 128, COUT / 128);     // (128, 2) = 256 CTAs, one wave
    gemm_kernel<<<grid, 256, NSTAGE * STAGEB>>>(bias, out);
}

// round 13
// speedup vs baseline: 1.7215x; 1.0041x over previous
#include <cuda_runtime.h>
#include <cuda_fp16.h>
#include <cstdint>

#define IMH 64
#define IMW 64
#define HW 4096
#define CIN 256
#define COUT 256
#define KKTAP 9
#define KDIM 2304            // k' = kk*256 + c
#define NDIM 16384

// cols_T: [NDIM][KDIM] fp16 (row = 4608 B)  — B operand, K-major
__device__ uint4 g_colsT4[(size_t)NDIM * 288];
// repacked weight: [COUT][KDIM] fp16, same k' order — A operand, K-major
__device__ uint4 g_wr4[(size_t)COUT * 288];
// NHWC parity-pair x: [b*64+row][wq][c] as half2 words.
__device__ uint32_t g_xh2[(size_t)4 * IMH * 64 * CIN];

__device__ __forceinline__ uint32_t smem_u32(const void* p) {
    return (uint32_t)__cvta_generic_to_shared(p);
}
__device__ __forceinline__ void cp16(uint32_t d, const void* s) {
    asm volatile("cp.async.cg.shared.global [%0], [%1], 16;" :: "r"(d), "l"(s) : "memory");
}
#define CP_COMMIT() asm volatile("cp.async.commit_group;" ::: "memory")
#define CP_WAIT1()  asm volatile("cp.async.wait_group 1;" ::: "memory")

#define LDSM_X4(r0, r1, r2, r3, a)                                          \
    asm volatile("ldmatrix.sync.aligned.m8n8.x4.shared.b16 {%0,%1,%2,%3}, [%4];" \
                 : "=r"(r0), "=r"(r1), "=r"(r2), "=r"(r3) : "r"(a))

#define MMA16816(c, av, bv0, bv1)                                           \
    asm volatile("mma.sync.aligned.m16n8k16.row.col.f32.f16.f16.f32 "       \
                 "{%0,%1,%2,%3}, {%4,%5,%6,%7}, {%8,%9}, {%0,%1,%2,%3};"    \
                 : "+f"((c)[0]), "+f"((c)[1]), "+f"((c)[2]), "+f"((c)[3])   \
                 : "r"((av)[0]), "r"((av)[1]), "r"((av)[2]), "r"((av)[3]),  \
                   "r"(bv0), "r"(bv1))

// ---------------- Kernel A: x NCHW fp32 -> NHWC parity-pair fp16 -----------
__global__ __launch_bounds__(256) void xpack_kernel(const float* __restrict__ x) {
    const int blk = blockIdx.x;            // b*64 + row
    const int c = threadIdx.x;
    const float* src = x + ((size_t)(blk >> 6) * CIN + c) * HW + (blk & 63) * 64;
    float v[64];
    #pragma unroll
    for (int i = 0; i < 16; i++) {
        float4 t = reinterpret_cast<const float4*>(src)[i];
        v[4 * i] = t.x; v[4 * i + 1] = t.y; v[4 * i + 2] = t.z; v[4 * i + 3] = t.w;
    }
    uint32_t w[64];
    #pragma unroll
    for (int j = 0; j < 32; j++) {
        __half2 h = __floats2half2_rn(v[2 * j], v[2 * j + 1]);
        w[j] = *reinterpret_cast<uint32_t*>(&h);
    }
    #pragma unroll
    for (int j = 0; j < 32; j++) {
        float nx = (j == 31) ? v[63] : v[2 * j + 2];
        __half2 h = __floats2half2_rn(v[2 * j + 1], nx);
        w[32 + j] = *reinterpret_cast<uint32_t*>(&h);
    }
    uint32_t* dst = g_xh2 + (size_t)blk * 64 * 256 + c;
    #pragma unroll
    for (int q = 0; q < 64; q++) dst[q * 256] = w[q];   // coalesced across c
}

// ---------------- Kernel 0: weight repack fp32->fp16, k' = kk*256+c --------
__global__ __launch_bounds__(512) void repack_kernel(const float* __restrict__ w) {
    int idx = blockIdx.x * 512 + threadIdx.x;
    int o = idx / KDIM;
    int r = idx - o * KDIM;
    int kk = r >> 8;
    int c = r & 255;
    reinterpret_cast<__half*>(g_wr4)[idx] = __float2half(w[(o * CIN + c) * KKTAP + kk]);
}

// ---------------- Kernel 1: gather, warp = one tap, coalesced NHWC ---------
__global__ __launch_bounds__(256) void gather_kernel(const float* __restrict__ offset) {
    const int gw = (blockIdx.x * 256 + threadIdx.x) >> 5;   // tap id < 147456
    const int lane = threadIdx.x & 31;
    const int n = gw / 9;
    const int kk = gw - n * 9;
    const int b = n >> 12, hw = n & 4095, ho = hw >> 6, wo = hw & 63;

    const float* offb = offset + (size_t)b * (2 * KKTAP) * HW;
    float offy = offb[(2 * kk) * HW + hw];                  // warp-broadcast
    float offx = offb[(2 * kk + 1) * HW + hw];
    float py = (float)(ho - 1 + kk / 3) + offy;
    float px = (float)(wo - 1 + kk % 3) + offx;

    float fy = floorf(py), fx = floorf(px);
    float ly = py - fy, lx = px - fx;
    int y0 = (int)fy, x0 = (int)fx, y1 = y0 + 1, x1 = x0 + 1;
    bool vy0 = (y0 >= 0) & (y0 < IMH), vy1 = (y1 >= 0) & (y1 < IMH);
    bool vx0 = (x0 >= 0) & (x0 < IMW), vx1 = (x1 >= 0) & (x1 < IMW);
    float w00 = (1.f - ly) * (1.f - lx) * (float)(vy0 & vx0);
    float w01 = (1.f - ly) * lx * (float)(vy0 & vx1);
    float w10 = ly * (1.f - lx) * (float)(vy1 & vx0);
    float w11 = ly * lx * (float)(vy1 & vx1);

    int qx = min(max(x0, 0), 62);
    int wq = (qx & 1) ? (32 + (qx >> 1)) : (qx >> 1);
    bool sel0 = (x0 == qx);
    bool sel1 = (x1 == qx);
    float wl0 = (sel0 ? w00 : 0.f) + (sel1 ? w01 : 0.f);
    float wh0 = (sel0 ? 0.f : w00) + (sel1 ? 0.f : w01);
    float wl1 = (sel0 ? w10 : 0.f) + (sel1 ? w11 : 0.f);
    float wh1 = (sel0 ? 0.f : w10) + (sel1 ? 0.f : w11);

    int cy0 = min(max(y0, 0), IMH - 1), cy1 = min(max(y1, 0), IMH - 1);
    const uint32_t* r0 = g_xh2 + (((size_t)(b * 64 + cy0) * 64 + wq) << 8);
    const uint32_t* r1 = g_xh2 + (((size_t)(b * 64 + cy1) * 64 + wq) << 8);
    __half* orow = reinterpret_cast<__half*>(g_colsT4) + (size_t)n * KDIM + kk * 256;

    #pragma unroll
    for (int g = 0; g < 2; g++) {
        const int cb = g * 128 + 4 * lane;             // 4 channels per lane
        uint4 pa = *reinterpret_cast<const uint4*>(r0 + cb);
        uint4 pb = *reinterpret_cast<const uint4*>(r1 + cb);
        const uint32_t* au = &pa.x;
        const uint32_t* bu = &pb.x;
        uint32_t h[2];
        #pragma unroll
        for (int q = 0; q < 2; q++) {
            float o2[2];
            #pragma unroll
            for (int j = 0; j < 2; j++) {
                uint32_t aw = au[2 * q + j], bw = bu[2 * q + j];
                float2 fa = __half22float2(*reinterpret_cast<__half2*>(&aw));
                float2 fb = __half22float2(*reinterpret_cast<__half2*>(&bw));
                o2[j] = wl0 * fa.x + wh0 * fa.y + wl1 * fb.x + wh1 * fb.y;
            }
            __half2 hh = __floats2half2_rn(o2[0], o2[1]);
            h[q] = *reinterpret_cast<uint32_t*>(&hh);
        }
        *reinterpret_cast<uint2*>(orow + cb) = make_uint2(h[0], h[1]);
    }
}

// ---------------- Kernel 2: HMMA fp16 GEMM, 128x128, BK=64, 3 stages -------
// 8 warps (warp 32m x 64n), 256 CTAs = single wave at 2 CTAs/SM.
// Distance-2 prefetch + wait_group 1: one stage-load always in flight under
// compute. One commit per iteration (empty at tail) keeps accounting uniform.
#define ROWB 144                           // 64 K-halfs = 128B data + 16 pad
#define ATILEB (128 * ROWB)                // 18432
#define BTILEB (128 * ROWB)                // 18432
#define STAGEB (ATILEB + BTILEB)           // 36864
#define NSTAGE 3
#define KITER (KDIM / 64)                  // 36

__global__ __launch_bounds__(256, 2) void gemm_kernel(const float* __restrict__ bias,
                                                      float* __restrict__ out) {
    extern __shared__ unsigned char smraw[];
    const uint32_t su = smem_u32(smraw);
    const int tid = threadIdx.x;
    const int wid = tid >> 5, lane = tid & 31;
    const int warp_m = wid & 3;            // 4 warps over m (32 each)
    const int warp_n = wid >> 2;           // 2 warps over n (64 each)
    const int bm = blockIdx.y * 128, bn = blockIdx.x * 128;

    const __half* gA0 = reinterpret_cast<const __half*>(g_wr4) + (size_t)bm * KDIM;
    const __half* gB0 = reinterpret_cast<const __half*>(g_colsT4) + (size_t)bn * KDIM;

    auto load_stage = [&](int it, int s) {
        uint32_t sA = su + s * STAGEB;
        uint32_t sB = sA + ATILEB;
        const __half* ga = gA0 + it * 64;
        const __half* gb = gB0 + it * 64;
        #pragma unroll
        for (int i = 0; i < 4; i++) {                 // A: 1024 16B-chunks
            int idx = i * 256 + tid, row = idx >> 3, c = idx & 7;
            cp16(sA + row * ROWB + c * 16, ga + (size_t)row * KDIM + c * 8);
        }
        #pragma unroll
        for (int i = 0; i < 4; i++) {                 // B: 1024 16B-chunks
            int idx = i * 256 + tid, row = idx >> 3, c = idx & 7;
            cp16(sB + row * ROWB + c * 16, gb + (size_t)row * KDIM + c * 8);
        }
        CP_COMMIT();
    };

    float acc[2][8][4];
    #pragma unroll
    for (int i = 0; i < 2; i++)
        #pragma unroll
        for (int j = 0; j < 8; j++)
            #pragma unroll
            for (int q = 0; q < 4; q++) acc[i][j][q] = 0.f;

    load_stage(0, 0);
    load_stage(1, 1);
    CP_WAIT1();                            // stage 0 landed, stage 1 in flight
    __syncthreads();

    const uint32_t aoff = (uint32_t)(warp_m * 32 + (lane & 15)) * ROWB + ((lane >> 4) << 4);
    const uint32_t boff = (uint32_t)(warp_n * 64 + (lane & 7) + ((lane >> 4) << 3)) * ROWB +
                          (((lane >> 3) & 1) << 4);

    for (int it = 0; it < KITER; it++) {
        if (it + 2 < KITER) load_stage(it + 2, (it + 2) % NSTAGE);
        else                CP_COMMIT();   // empty group, keeps WAIT1 exact

        const uint32_t sA = su + (it % NSTAGE) * STAGEB;
        const uint32_t sB = sA + ATILEB;
        #pragma unroll
        for (int ks = 0; ks < 4; ks++) {
            uint32_t a[2][4], b[8][2];
            #pragma unroll
            for (int mt = 0; mt < 2; mt++)
                LDSM_X4(a[mt][0], a[mt][1], a[mt][2], a[mt][3],
                        sA + aoff + mt * 16 * ROWB + ks * 32);
            #pragma unroll
            for (int q = 0; q < 4; q++)
                LDSM_X4(b[2 * q][0], b[2 * q][1], b[2 * q + 1][0], b[2 * q + 1][1],
                        sB + boff + q * 16 * ROWB + ks * 32);
            #pragma unroll
            for (int mt = 0; mt < 2; mt++)
                #pragma unroll
                for (int nt = 0; nt < 8; nt++)
                    MMA16816(acc[mt][nt], a[mt], b[nt][0], b[nt][1]);
        }
        CP_WAIT1();                        // stage it+1 landed before next iter
        __syncthreads();
    }

    const int g = lane >> 2, t2 = (lane & 3) * 2;
    const int b_img = bn >> 12;
    const int hw0 = bn & 4095;
    #pragma unroll
    for (int mt = 0; mt < 2; mt++) {
        int m0 = bm + warp_m * 32 + mt * 16 + g;
        float bv0 = __ldg(&bias[m0]);
        float bv1 = __ldg(&bias[m0 + 8]);
        float* row0 = out + ((size_t)b_img * COUT + m0) * HW + hw0;
        float* row1 = row0 + 8 * HW;
        #pragma unroll
        for (int nt = 0; nt < 8; nt++) {
            int nc = warp_n * 64 + nt * 8 + t2;
            *reinterpret_cast<float2*>(row0 + nc) =
                make_float2(acc[mt][nt][0] + bv0, acc[mt][nt][1] + bv0);
            *reinterpret_cast<float2*>(row1 + nc) =
                make_float2(acc[mt][nt][2] + bv1, acc[mt][nt][3] + bv1);
        }
    }
}

// ---------------------------------------------------------------------------
extern "C" void kernel_launch(void* const* d_in, const int* in_sizes, int n_in,
                              void* d_out, int out_size) {
    const float* x      = (const float*)d_in[0];
    const float* offset = (const float*)d_in[1];
    const float* weight = (const float*)d_in[2];
    const float* bias   = (const float*)d_in[3];
    float* out = (float*)d_out;

    xpack_kernel<<<4 * IMH, 256>>>(x);                    // 256 blocks
    repack_kernel<<<COUT * KDIM / 512, 512>>>(weight);
    gather_kernel<<<NDIM * KKTAP / 8, 256>>>(offset);     // 18432 blocks

    cudaFuncSetAttribute(gemm_kernel, cudaFuncAttributeMaxDynamicSharedMemorySize,
                         NSTAGE * STAGEB);
    dim3 grid(NDIM / 128, COUT / 128);     // (128, 2) = 256 CTAs, one wave
    gemm_kernel<<<grid, 256, NSTAGE * STAGEB>>>(bias, out);
}